// round 13
// baseline (speedup 1.0000x reference)
#include <cuda_runtime.h>
#include <math.h>

#define M_ROWS 8192
#define N_COLS 16384
#define K_DIM  512
#define RPB    8      // X rows per block
#define CAP    64     // candidate capacity per row
#define FLT_MIN_NORM 1.17549435e-38f

__global__ __launch_bounds__(256)
void fused_kernel(const float* __restrict__ X, const float* __restrict__ Y,
                  float* __restrict__ out) {
    __shared__ __align__(16) float xs[RPB][K_DIM];   // 16 KB
    __shared__ float s_red[RPB][256];                // 8 KB (max reduction)
    __shared__ float s_rowmax[RPB];
    __shared__ int   s_cnt[RPB];
    __shared__ int   s_idx[RPB][CAP];
    __shared__ float s_val[RPB][CAP];

    const int tid  = threadIdx.x;
    const int row0 = blockIdx.x * RPB;

    // Coalesced load of the 8 X rows into smem.
    {
        const float4* xsrc = (const float4*)(X + (size_t)row0 * K_DIM);
        float4* xdst = (float4*)&xs[0][0];
        #pragma unroll
        for (int j = 0; j < 4; j++)
            xdst[tid + j * 256] = xsrc[tid + j * 256];
    }
    if (tid < RPB) s_cnt[tid] = 0;
    __syncthreads();

    // ---------------- Pass 1: exact per-row max ----------------
    float tmax[RPB];
    #pragma unroll
    for (int r = 0; r < RPB; r++) tmax[r] = -3.402823466e+38f;

    for (int yb = 0; yb < N_COLS; yb += 256) {
        const float4* yp = (const float4*)(Y + (size_t)(yb + tid) * K_DIM);
        float acc[RPB];
        #pragma unroll
        for (int r = 0; r < RPB; r++) acc[r] = 0.0f;
        #pragma unroll 4
        for (int k4 = 0; k4 < K_DIM / 4; k4++) {
            float4 yv = yp[k4];
            #pragma unroll
            for (int r = 0; r < RPB; r++) {
                float4 xv = *(const float4*)&xs[r][k4 * 4];
                float a = acc[r];
                a = fmaf(xv.x, yv.x, a);
                a = fmaf(xv.y, yv.y, a);
                a = fmaf(xv.z, yv.z, a);
                a = fmaf(xv.w, yv.w, a);
                acc[r] = a;
            }
        }
        #pragma unroll
        for (int r = 0; r < RPB; r++)
            tmax[r] = fmaxf(tmax[r], __fdiv_rn(acc[r], 0.07f));
    }

    #pragma unroll
    for (int r = 0; r < RPB; r++) s_red[r][tid] = tmax[r];
    __syncthreads();
    for (int s = 128; s > 0; s >>= 1) {
        if (tid < s) {
            #pragma unroll
            for (int r = 0; r < RPB; r++)
                s_red[r][tid] = fmaxf(s_red[r][tid], s_red[r][tid + s]);
        }
        __syncthreads();
    }
    if (tid < RPB) s_rowmax[tid] = s_red[tid][0];
    __syncthreads();

    float bar[RPB];
    #pragma unroll
    for (int r = 0; r < RPB; r++) bar[r] = s_rowmax[r] - 89.0f;

    // ---------------- Pass 2: recompute, collect candidates ----------------
    // Identical FMA sequence -> bit-identical values vs pass 1.
    // Ranked set is {v : exp(v - lse) >= FLT_MIN} with lse >= m, so
    // v > m - 87.34 suffices; bar = m - 89 adds margin.
    for (int yb = 0; yb < N_COLS; yb += 256) {
        const int y = yb + tid;
        const float4* yp = (const float4*)(Y + (size_t)y * K_DIM);
        float acc[RPB];
        #pragma unroll
        for (int r = 0; r < RPB; r++) acc[r] = 0.0f;
        #pragma unroll 4
        for (int k4 = 0; k4 < K_DIM / 4; k4++) {
            float4 yv = yp[k4];
            #pragma unroll
            for (int r = 0; r < RPB; r++) {
                float4 xv = *(const float4*)&xs[r][k4 * 4];
                float a = acc[r];
                a = fmaf(xv.x, yv.x, a);
                a = fmaf(xv.y, yv.y, a);
                a = fmaf(xv.z, yv.z, a);
                a = fmaf(xv.w, yv.w, a);
                acc[r] = a;
            }
        }
        #pragma unroll
        for (int r = 0; r < RPB; r++) {
            float v = __fdiv_rn(acc[r], 0.07f);
            if (v > bar[r]) {
                int p = atomicAdd(&s_cnt[r], 1);
                if (p < CAP) { s_idx[r][p] = y; s_val[r][p] = v; }
            }
        }
    }
    __syncthreads();

    // ---------------- Finalize: one thread per row ----------------
    // Reference semantics (per problem statement): P = exp(sim - logsumexp(sim)),
    // fp32 with flush-to-zero at the normal-float boundary.
    if (tid < RPB) {
        const int r = tid;
        const float m = s_rowmax[r];
        int n = s_cnt[r]; if (n > CAP) n = CAP;

        // Sort candidates by index ascending (canonical deterministic order).
        for (int i = 1; i < n; i++) {
            int ii = s_idx[r][i]; float vv = s_val[r][i];
            int j = i - 1;
            while (j >= 0 && s_idx[r][j] > ii) {
                s_idx[r][j + 1] = s_idx[r][j];
                s_val[r][j + 1] = s_val[r][j];
                j--;
            }
            s_idx[r][j + 1] = ii; s_val[r][j + 1] = vv;
        }

        // sum = sum_i exp(v_i - m) with FTZ-at-normal semantics (elements below
        // the bar contribute exact 0; near-floor normals contribute ~1e-38,
        // irrelevant to the fp32 sum ~ 1).
        float sum = 0.0f;
        for (int i = 0; i < n; i++) {
            float d = __fsub_rn(s_val[r][i], m);
            float p = (float)exp((double)d);
            if (p < FLT_MIN_NORM) p = 0.0f;
            sum = __fadd_rn(sum, p);
        }
        // lse = m + log(sum), all fp32 roundings explicit.
        float lse = __fadd_rn(m, (float)log((double)sum));

        // P_i = exp(v_i - lse), flushed below the normal boundary.
        for (int i = 0; i < n; i++) {
            float d = __fsub_rn(s_val[r][i], lse);
            float p = (float)exp((double)d);
            if (p < FLT_MIN_NORM) p = 0.0f;
            s_val[r][i] = p;
        }

        // Emit nonzero-P candidates by (P desc, idx asc). Output as float32.
        int used[16];
        int ne = 0;
        float* orow = out + (size_t)(row0 + r) * 16;
        for (int slot = 0; slot < 16; slot++) {
            int best = -1; float bp = 0.0f;
            for (int i = 0; i < n; i++)
                if (s_val[r][i] > bp) { bp = s_val[r][i]; best = i; } // ties -> lowest idx
            if (best < 0) break;
            orow[ne] = (float)s_idx[r][best];
            used[ne] = s_idx[r][best];
            ne++;
            s_val[r][best] = -1.0f;
        }

        // Remaining slots: zero-tie block -> stable top_k fills with the
        // smallest indices not already emitted.
        int written = ne, v = 0;
        while (written < 16) {
            bool u = false;
            for (int i = 0; i < ne; i++)
                if (used[i] == v) { u = true; break; }
            if (!u) orow[written++] = (float)v;
            v++;
        }
    }
}

extern "C" void kernel_launch(void* const* d_in, const int* in_sizes, int n_in,
                              void* d_out, int out_size) {
    // Robust input identification: X has 8192*512 elements, Y has 16384*512.
    const float* X = (const float*)d_in[0];
    const float* Y = (const float*)d_in[1];
    if (in_sizes[0] == N_COLS * K_DIM && in_sizes[1] == M_ROWS * K_DIM) {
        X = (const float*)d_in[1];
        Y = (const float*)d_in[0];
    }
    float* out = (float*)d_out;

    fused_kernel<<<M_ROWS / RPB, 256>>>(X, Y, out);
}

// round 14
// speedup vs baseline: 3.2049x; 3.2049x over previous
#include <cuda_runtime.h>
#include <math.h>

#define M_ROWS 8192
#define N_COLS 16384
#define K_DIM  512

#define BM 64
#define BN 128
#define BK 16
#define NSTRIP (N_COLS / BN)
#define CAP 64
#define FLT_MIN_NORM 1.17549435e-38f

// Monotone float <-> uint encoding for atomicMax on floats (incl. negatives).
__device__ __forceinline__ unsigned f2ord(float f) {
    unsigned b = __float_as_uint(f);
    return (b & 0x80000000u) ? ~b : (b | 0x80000000u);
}
__device__ __forceinline__ float ord2f(unsigned u) {
    unsigned b = (u & 0x80000000u) ? (u & 0x7fffffffu) : ~u;
    return __uint_as_float(b);
}
#define ORD_NEG_MAX 0x00800000u   // f2ord(-FLT_MAX)

// Candidate margin in acc (pre-division) domain: 6.35 / 0.07 = 90.7 sim units,
// comfortably above the 87.34 FTZ cutoff + lse shift + cross-impl margin.
#define ACC_MARGIN 6.35f

__global__ __launch_bounds__(256)
void fused_gemm_topk(const float* __restrict__ X, const float* __restrict__ Y,
                     float* __restrict__ out) {
    __shared__ float As[BK][BM + 4];
    __shared__ float Bs[BK][BN + 8];
    __shared__ unsigned s_bar[BM];     // row max in acc domain (ordered uint)
    __shared__ int      s_cnt[BM];
    __shared__ int      s_idx[BM][CAP];
    __shared__ float    s_acc[BM][CAP];

    const int tid = threadIdx.x;
    const int m0  = blockIdx.x * BM;
    const int tx  = tid & 15;    // 16 n-groups of 8
    const int ty  = tid >> 4;    // 16 m-groups of 4

    if (tid < BM) { s_bar[tid] = ORD_NEG_MAX; s_cnt[tid] = 0; }
    __syncthreads();

    for (int strip = 0; strip < NSTRIP; strip++) {
        const int y0 = strip * BN;
        float acc[4][8] = {};

        for (int k0 = 0; k0 < K_DIM; k0 += BK) {
            // Load A tile (64x16) transposed to k-major: 1 float4 per thread.
            {
                int row = tid >> 2, kc = (tid & 3) * 4;
                float4 a = *(const float4*)&X[(size_t)(m0 + row) * K_DIM + k0 + kc];
                As[kc + 0][row] = a.x; As[kc + 1][row] = a.y;
                As[kc + 2][row] = a.z; As[kc + 3][row] = a.w;
            }
            // Load B tile (128x16) transposed: 2 float4 per thread.
            #pragma unroll
            for (int i = 0; i < 2; i++) {
                int idx = tid + i * 256;
                int row = idx >> 2, kc = (idx & 3) * 4;
                float4 b = *(const float4*)&Y[(size_t)(y0 + row) * K_DIM + k0 + kc];
                Bs[kc + 0][row] = b.x; Bs[kc + 1][row] = b.y;
                Bs[kc + 2][row] = b.z; Bs[kc + 3][row] = b.w;
            }
            __syncthreads();

            #pragma unroll
            for (int k = 0; k < BK; k++) {
                float4 a0 = *(const float4*)&As[k][ty * 4];
                float4 b0 = *(const float4*)&Bs[k][tx * 8];
                float4 b1 = *(const float4*)&Bs[k][tx * 8 + 4];
                float ar[4] = {a0.x, a0.y, a0.z, a0.w};
                float br[8] = {b0.x, b0.y, b0.z, b0.w, b1.x, b1.y, b1.z, b1.w};
                #pragma unroll
                for (int i = 0; i < 4; i++)
                    #pragma unroll
                    for (int j = 0; j < 8; j++)
                        acc[i][j] = fmaf(ar[i], br[j], acc[i][j]);
            }
            __syncthreads();
        }

        // Epilogue: running-bar candidate collection (acc domain).
        // Bar is monotone nondecreasing; stale reads are permissive => the
        // candidate set is always a superset of the final survivors.
        #pragma unroll
        for (int i = 0; i < 4; i++) {
            const int r = ty * 4 + i;
            float lmax = acc[i][0];
            #pragma unroll
            for (int j = 1; j < 8; j++) lmax = fmaxf(lmax, acc[i][j]);
            float cur = ord2f(*(volatile unsigned*)&s_bar[r]);
            if (lmax > cur) { atomicMax(&s_bar[r], f2ord(lmax)); cur = lmax; }
            const float barv = cur - ACC_MARGIN;
            #pragma unroll
            for (int j = 0; j < 8; j++) {
                if (acc[i][j] > barv) {
                    int p = atomicAdd(&s_cnt[r], 1);
                    if (p < CAP) {
                        s_idx[r][p] = y0 + tx * 8 + j;
                        s_acc[r][p] = acc[i][j];
                    }
                }
            }
        }
        __syncthreads();

        // Compaction: keep lists small. Drops only items provably below the
        // final bar (current bar <= final bar).
        if (tid < BM && s_cnt[tid] > 24) {
            const int r = tid;
            float b = ord2f(s_bar[r]) - ACC_MARGIN;
            int n = s_cnt[r]; if (n > CAP) n = CAP;
            int w = 0;
            for (int i2 = 0; i2 < n; i2++) {
                if (s_acc[r][i2] > b) {
                    s_acc[r][w] = s_acc[r][i2];
                    s_idx[r][w] = s_idx[r][i2];
                    w++;
                }
            }
            s_cnt[r] = w;
        }
        __syncthreads();
    }

    // ---------------- Finalize: one thread per row ----------------
    // Exact semantics identical to the passing R13 kernel: v = rn(acc/0.07),
    // P = exp(v - lse) with flush below the fp32 normal boundary, rank by
    // (P desc, idx asc), zero-tie block filled with smallest unused indices.
    if (tid < BM) {
        const int r = tid;
        const float maxacc = ord2f(s_bar[r]);
        const float m = __fdiv_rn(maxacc, 0.07f);
        int n = s_cnt[r]; if (n > CAP) n = CAP;

        // Exact v for each candidate.
        float vv[CAP];
        int   vi[CAP];
        for (int i = 0; i < n; i++) {
            vv[i] = __fdiv_rn(s_acc[r][i], 0.07f);
            vi[i] = s_idx[r][i];
        }

        // Sort by index ascending (canonical deterministic order).
        for (int i = 1; i < n; i++) {
            int ii = vi[i]; float tv = vv[i];
            int j = i - 1;
            while (j >= 0 && vi[j] > ii) {
                vi[j + 1] = vi[j]; vv[j + 1] = vv[j]; j--;
            }
            vi[j + 1] = ii; vv[j + 1] = tv;
        }

        // sum = sum exp(v - m), FTZ at the normal boundary.
        float sum = 0.0f;
        for (int i = 0; i < n; i++) {
            float d = __fsub_rn(vv[i], m);
            float p = (float)exp((double)d);
            if (p < FLT_MIN_NORM) p = 0.0f;
            sum = __fadd_rn(sum, p);
        }
        float lse = __fadd_rn(m, (float)log((double)sum));

        // P_i = exp(v_i - lse), flushed below the normal boundary.
        float pv[CAP];
        for (int i = 0; i < n; i++) {
            float d = __fsub_rn(vv[i], lse);
            float p = (float)exp((double)d);
            if (p < FLT_MIN_NORM) p = 0.0f;
            pv[i] = p;
        }

        // Emit nonzero-P candidates by (P desc, idx asc). Output as float32.
        int used[16];
        int ne = 0;
        float* orow = out + (size_t)(m0 + r) * 16;
        for (int slot = 0; slot < 16; slot++) {
            int best = -1; float bp = 0.0f;
            for (int i = 0; i < n; i++)
                if (pv[i] > bp) { bp = pv[i]; best = i; }   // ties -> lowest idx
            if (best < 0) break;
            orow[ne] = (float)vi[best];
            used[ne] = vi[best];
            ne++;
            pv[best] = -1.0f;
        }

        // Zero-tie block: fill with the smallest indices not already emitted.
        int written = ne, v = 0;
        while (written < 16) {
            bool u = false;
            for (int i = 0; i < ne; i++)
                if (used[i] == v) { u = true; break; }
            if (!u) orow[written++] = (float)v;
            v++;
        }
    }
}

extern "C" void kernel_launch(void* const* d_in, const int* in_sizes, int n_in,
                              void* d_out, int out_size) {
    // Robust input identification: X has 8192*512 elements, Y has 16384*512.
    const float* X = (const float*)d_in[0];
    const float* Y = (const float*)d_in[1];
    if (in_sizes[0] == N_COLS * K_DIM && in_sizes[1] == M_ROWS * K_DIM) {
        X = (const float*)d_in[1];
        Y = (const float*)d_in[0];
    }
    float* out = (float*)d_out;

    fused_gemm_topk<<<M_ROWS / BM, 256>>>(X, Y, out);
}

// round 15
// speedup vs baseline: 3.6885x; 1.1509x over previous
#include <cuda_runtime.h>
#include <math.h>

#define M_ROWS 8192
#define N_COLS 16384
#define K_DIM  512

#define BM 64
#define BN 128
#define BK 16
#define NS 4                        // N-dimension slices (grid.y)
#define SLICE_COLS (N_COLS / NS)    // 4096
#define NSTRIP (SLICE_COLS / BN)    // 32
#define CAP 64
#define FLT_MIN_NORM 1.17549435e-38f

// Candidate margin in acc (pre-division) domain: 6.35/0.07 = 90.7 sim units,
// above the 87.34 FTZ cutoff + lse shift + cross-impl margin.
#define ACC_MARGIN 6.35f

// Monotone float <-> uint encoding for atomicMax on floats (incl. negatives).
__device__ __forceinline__ unsigned f2ord(float f) {
    unsigned b = __float_as_uint(f);
    return (b & 0x80000000u) ? ~b : (b | 0x80000000u);
}
__device__ __forceinline__ float ord2f(unsigned u) {
    unsigned b = (u & 0x80000000u) ? (u & 0x7fffffffu) : ~u;
    return __uint_as_float(b);
}
#define ORD_NEG_MAX 0x00800000u   // f2ord(-FLT_MAX)

// Per-(row, slice) scratch: slice max (acc domain), candidate count + lists.
__device__ unsigned g_bar[(size_t)M_ROWS * NS];
__device__ int      g_cnt[(size_t)M_ROWS * NS];
__device__ int      g_cidx[(size_t)M_ROWS * NS * CAP];
__device__ float    g_cacc[(size_t)M_ROWS * NS * CAP];

// ---------------------------------------------------------------------------
// Kernel 1: GEMM slice + candidate collection (identical value path to R14).
// ---------------------------------------------------------------------------
__global__ __launch_bounds__(256, 4)
void gemm_collect(const float* __restrict__ X, const float* __restrict__ Y) {
    __shared__ float As[BK][BM + 4];
    __shared__ float Bs[BK][BN + 8];
    __shared__ unsigned s_bar[BM];
    __shared__ int      s_cnt[BM];
    __shared__ int      s_idx[BM][CAP];
    __shared__ float    s_acc[BM][CAP];

    const int tid = threadIdx.x;
    const int m0  = blockIdx.x * BM;
    const int s0  = blockIdx.y * SLICE_COLS;
    const int tx  = tid & 15;
    const int ty  = tid >> 4;

    if (tid < BM) { s_bar[tid] = ORD_NEG_MAX; s_cnt[tid] = 0; }
    __syncthreads();

    for (int strip = 0; strip < NSTRIP; strip++) {
        const int y0 = s0 + strip * BN;
        float acc[4][8] = {};

        for (int k0 = 0; k0 < K_DIM; k0 += BK) {
            {
                int row = tid >> 2, kc = (tid & 3) * 4;
                float4 a = *(const float4*)&X[(size_t)(m0 + row) * K_DIM + k0 + kc];
                As[kc + 0][row] = a.x; As[kc + 1][row] = a.y;
                As[kc + 2][row] = a.z; As[kc + 3][row] = a.w;
            }
            #pragma unroll
            for (int i = 0; i < 2; i++) {
                int idx = tid + i * 256;
                int row = idx >> 2, kc = (idx & 3) * 4;
                float4 b = *(const float4*)&Y[(size_t)(y0 + row) * K_DIM + k0 + kc];
                Bs[kc + 0][row] = b.x; Bs[kc + 1][row] = b.y;
                Bs[kc + 2][row] = b.z; Bs[kc + 3][row] = b.w;
            }
            __syncthreads();

            #pragma unroll
            for (int k = 0; k < BK; k++) {
                float4 a0 = *(const float4*)&As[k][ty * 4];
                float4 b0 = *(const float4*)&Bs[k][tx * 8];
                float4 b1 = *(const float4*)&Bs[k][tx * 8 + 4];
                float ar[4] = {a0.x, a0.y, a0.z, a0.w};
                float br[8] = {b0.x, b0.y, b0.z, b0.w, b1.x, b1.y, b1.z, b1.w};
                #pragma unroll
                for (int i = 0; i < 4; i++)
                    #pragma unroll
                    for (int j = 0; j < 8; j++)
                        acc[i][j] = fmaf(ar[i], br[j], acc[i][j]);
            }
            __syncthreads();
        }

        // Running-bar candidate collection (acc domain). Bar is monotone;
        // stale reads are permissive => candidate superset. Same as R14.
        #pragma unroll
        for (int i = 0; i < 4; i++) {
            const int r = ty * 4 + i;
            float lmax = acc[i][0];
            #pragma unroll
            for (int j = 1; j < 8; j++) lmax = fmaxf(lmax, acc[i][j]);
            float cur = ord2f(*(volatile unsigned*)&s_bar[r]);
            if (lmax > cur) { atomicMax(&s_bar[r], f2ord(lmax)); cur = lmax; }
            const float barv = cur - ACC_MARGIN;
            #pragma unroll
            for (int j = 0; j < 8; j++) {
                if (acc[i][j] > barv) {
                    int p = atomicAdd(&s_cnt[r], 1);
                    if (p < CAP) {
                        s_idx[r][p] = y0 + tx * 8 + j;
                        s_acc[r][p] = acc[i][j];
                    }
                }
            }
        }
        __syncthreads();

        if (tid < BM && s_cnt[tid] > 24) {
            const int r = tid;
            float b = ord2f(s_bar[r]) - ACC_MARGIN;
            int n = s_cnt[r]; if (n > CAP) n = CAP;
            int w = 0;
            for (int i2 = 0; i2 < n; i2++) {
                if (s_acc[r][i2] > b) {
                    s_acc[r][w] = s_acc[r][i2];
                    s_idx[r][w] = s_idx[r][i2];
                    w++;
                }
            }
            s_cnt[r] = w;
        }
        __syncthreads();
    }

    // Dump final per-slice state (filtered vs final slice bar) to scratch.
    if (tid < BM) {
        const int r = tid;
        const unsigned barv = s_bar[r];
        const float bf = ord2f(barv) - ACC_MARGIN;
        int n = s_cnt[r]; if (n > CAP) n = CAP;

        const size_t base = ((size_t)(m0 + r) * NS + blockIdx.y);
        int w = 0;
        for (int i = 0; i < n; i++) {
            if (s_acc[r][i] > bf) {
                g_cidx[base * CAP + w] = s_idx[r][i];
                g_cacc[base * CAP + w] = s_acc[r][i];
                w++;
            }
        }
        g_bar[base] = barv;
        g_cnt[base] = w;
    }
}

// ---------------------------------------------------------------------------
// Kernel 2: merge slices + finalize (verbatim R14 semantics).
// One thread per row.
// ---------------------------------------------------------------------------
__global__ __launch_bounds__(256)
void merge_finalize(float* __restrict__ out) {
    const int row = blockIdx.x * 256 + threadIdx.x;
    if (row >= M_ROWS) return;

    // Global row max (acc domain) over slices.
    float maxacc = -3.402823466e+38f;
    #pragma unroll
    for (int s = 0; s < NS; s++)
        maxacc = fmaxf(maxacc, ord2f(g_bar[(size_t)row * NS + s]));

    const float barv = maxacc - ACC_MARGIN;

    // Gather candidates above the global bar.
    float av[CAP];
    int   vi[CAP];
    int n = 0;
    #pragma unroll
    for (int s = 0; s < NS; s++) {
        const size_t base = ((size_t)row * NS + s);
        int c = g_cnt[base]; if (c > CAP) c = CAP;
        for (int i = 0; i < c; i++) {
            float a = g_cacc[base * CAP + i];
            if (a > barv && n < CAP) {
                av[n] = a;
                vi[n] = g_cidx[base * CAP + i];
                n++;
            }
        }
    }

    // Exact v = rn(acc / 0.07).
    const float m = __fdiv_rn(maxacc, 0.07f);
    float vv[CAP];
    for (int i = 0; i < n; i++) vv[i] = __fdiv_rn(av[i], 0.07f);

    // Sort by index ascending (canonical deterministic order).
    for (int i = 1; i < n; i++) {
        int ii = vi[i]; float tv = vv[i];
        int j = i - 1;
        while (j >= 0 && vi[j] > ii) {
            vi[j + 1] = vi[j]; vv[j + 1] = vv[j]; j--;
        }
        vi[j + 1] = ii; vv[j + 1] = tv;
    }

    // sum = sum exp(v - m), FTZ at the fp32 normal boundary.
    float sum = 0.0f;
    for (int i = 0; i < n; i++) {
        float d = __fsub_rn(vv[i], m);
        float p = (float)exp((double)d);
        if (p < FLT_MIN_NORM) p = 0.0f;
        sum = __fadd_rn(sum, p);
    }
    float lse = __fadd_rn(m, (float)log((double)sum));

    // P_i = exp(v_i - lse), flushed below the normal boundary.
    float pv[CAP];
    for (int i = 0; i < n; i++) {
        float d = __fsub_rn(vv[i], lse);
        float p = (float)exp((double)d);
        if (p < FLT_MIN_NORM) p = 0.0f;
        pv[i] = p;
    }

    // Emit nonzero-P candidates by (P desc, idx asc). Output as float32.
    int used[16];
    int ne = 0;
    float* orow = out + (size_t)row * 16;
    for (int slot = 0; slot < 16; slot++) {
        int best = -1; float bp = 0.0f;
        for (int i = 0; i < n; i++)
            if (pv[i] > bp) { bp = pv[i]; best = i; }   // ties -> lowest idx
        if (best < 0) break;
        orow[ne] = (float)vi[best];
        used[ne] = vi[best];
        ne++;
        pv[best] = -1.0f;
    }

    // Zero-tie block: fill with smallest indices not already emitted.
    int written = ne, v = 0;
    while (written < 16) {
        bool u = false;
        for (int i = 0; i < ne; i++)
            if (used[i] == v) { u = true; break; }
        if (!u) orow[written++] = (float)v;
        v++;
    }
}

// ---------------------------------------------------------------------------
extern "C" void kernel_launch(void* const* d_in, const int* in_sizes, int n_in,
                              void* d_out, int out_size) {
    // Robust input identification: X has 8192*512 elements, Y has 16384*512.
    const float* X = (const float*)d_in[0];
    const float* Y = (const float*)d_in[1];
    if (in_sizes[0] == N_COLS * K_DIM && in_sizes[1] == M_ROWS * K_DIM) {
        X = (const float*)d_in[1];
        Y = (const float*)d_in[0];
    }
    float* out = (float*)d_out;

    dim3 grid(M_ROWS / BM, NS);
    gemm_collect<<<grid, 256>>>(X, Y);
    merge_finalize<<<M_ROWS / 256, 256>>>(out);
}

// round 17
// speedup vs baseline: 21.4280x; 5.8094x over previous
#include <cuda_runtime.h>
#include <math.h>
#include <stdint.h>

#define M_ROWS 8192
#define N_COLS 16384
#define K_DIM  512
#define CAP    512
#define RCAP   64
#define SCREEN_MARGIN 7.0f      // acc domain = 100 sim units
#define FLT_MIN_NORM 1.17549435e-38f

// Monotone float <-> uint for atomicMax on floats.
__device__ __forceinline__ unsigned f2ord(float f) {
    unsigned b = __float_as_uint(f);
    return (b & 0x80000000u) ? ~b : (b | 0x80000000u);
}
__device__ __forceinline__ float ord2f(unsigned u) {
    unsigned b = (u & 0x80000000u) ? (u & 0x7fffffffu) : ~u;
    return __uint_as_float(b);
}
#define ORD_NEG_MAX 0x00800000u

__device__ __forceinline__ uint32_t f32_to_tf32(float f) {
    uint32_t r;
    asm("cvt.rna.tf32.f32 %0, %1;" : "=r"(r) : "f"(f));
    return r;
}

__device__ __forceinline__ void mma_tf32(float d[4], const uint32_t a[4],
                                         const uint32_t b[2]) {
    asm volatile(
        "mma.sync.aligned.m16n8k8.row.col.f32.tf32.tf32.f32 "
        "{%0,%1,%2,%3}, {%4,%5,%6,%7}, {%8,%9}, {%0,%1,%2,%3};"
        : "+f"(d[0]), "+f"(d[1]), "+f"(d[2]), "+f"(d[3])
        : "r"(a[0]), "r"(a[1]), "r"(a[2]), "r"(a[3]), "r"(b[0]), "r"(b[1]));
}

// ---------------- Device scratch ----------------
__device__ unsigned g_barg[M_ROWS];
__device__ int      g_cnt[M_ROWS];
__device__ int      g_cidx[(size_t)M_ROWS * CAP];
__device__ float    g_cacc[(size_t)M_ROWS * CAP];

// ---------------------------------------------------------------------------
// Kernel 0: init per-row state.
// ---------------------------------------------------------------------------
__global__ void init_kernel() {
    int i = blockIdx.x * 256 + threadIdx.x;
    if (i < M_ROWS) { g_cnt[i] = 0; g_barg[i] = ORD_NEG_MAX; }
}

// ---------------------------------------------------------------------------
// Kernel 1: TF32 mma.sync screening GEMM (128x128 tile) + bar filter.
// 8 warps; each warp computes a 32x64 tile via m16n8k8 fragments.
// ---------------------------------------------------------------------------
#define PITCH 36

__global__ __launch_bounds__(256, 2)
void screen_gemm(const float* __restrict__ X, const float* __restrict__ Y) {
    __shared__ uint32_t As[128][PITCH];   // 18 KB
    __shared__ uint32_t Bs[128][PITCH];   // 18 KB

    const int tid  = threadIdx.x;
    const int wid  = tid >> 5;
    const int lane = tid & 31;
    const int m0 = blockIdx.x * 128;
    const int n0 = blockIdx.y * 128;
    const int wm = (wid >> 1) * 32;       // warp M offset in tile
    const int wn = (wid & 1) * 64;        // warp N offset in tile
    const int g  = lane >> 2;             // groupID
    const int t  = lane & 3;              // threadID_in_group

    float d[2][8][4] = {};

    for (int k0 = 0; k0 < K_DIM; k0 += 32) {
        // Stage 128x32 slabs of X and Y (converted to tf32 bits).
        #pragma unroll
        for (int u = 0; u < 4; u++) {
            int f = tid + u * 256;
            int row = f >> 3, kc = (f & 7) * 4;
            float4 a = *(const float4*)&X[(size_t)(m0 + row) * K_DIM + k0 + kc];
            uint4 ua = make_uint4(f32_to_tf32(a.x), f32_to_tf32(a.y),
                                  f32_to_tf32(a.z), f32_to_tf32(a.w));
            *(uint4*)&As[row][kc] = ua;
            float4 b = *(const float4*)&Y[(size_t)(n0 + row) * K_DIM + k0 + kc];
            uint4 ub = make_uint4(f32_to_tf32(b.x), f32_to_tf32(b.y),
                                  f32_to_tf32(b.z), f32_to_tf32(b.w));
            *(uint4*)&Bs[row][kc] = ub;
        }
        __syncthreads();

        #pragma unroll
        for (int ks = 0; ks < 4; ks++) {
            const int kk = ks * 8;
            uint32_t af[2][4];
            #pragma unroll
            for (int mi = 0; mi < 2; mi++) {
                const int r = wm + mi * 16;
                af[mi][0] = As[r + g    ][kk + t];
                af[mi][1] = As[r + g + 8][kk + t];
                af[mi][2] = As[r + g    ][kk + t + 4];
                af[mi][3] = As[r + g + 8][kk + t + 4];
            }
            #pragma unroll
            for (int nj = 0; nj < 8; nj++) {
                uint32_t bf[2];
                bf[0] = Bs[wn + nj * 8 + g][kk + t];
                bf[1] = Bs[wn + nj * 8 + g][kk + t + 4];
                #pragma unroll
                for (int mi = 0; mi < 2; mi++)
                    mma_tf32(d[mi][nj], af[mi], bf);
            }
        }
        __syncthreads();
    }

    // Epilogue: filter from registers vs global running bar.
    // D mapping (m16n8): c0/c1 -> row g, cols 2t/2t+1; c2/c3 -> row g+8.
    const int cb = n0 + wn + 2 * t;
    #pragma unroll
    for (int mi = 0; mi < 2; mi++) {
        #pragma unroll
        for (int half = 0; half < 2; half++) {
            const int row = m0 + wm + mi * 16 + g + half * 8;
            float lmax = -3.402823466e+38f;
            #pragma unroll
            for (int nj = 0; nj < 8; nj++) {
                lmax = fmaxf(lmax, d[mi][nj][half * 2]);
                lmax = fmaxf(lmax, d[mi][nj][half * 2 + 1]);
            }
            unsigned cur = *(volatile unsigned*)&g_barg[row];
            if (f2ord(lmax) > cur) cur = atomicMax(&g_barg[row], f2ord(lmax));
            float barv = fmaxf(ord2f(cur), lmax) - SCREEN_MARGIN;
            #pragma unroll
            for (int nj = 0; nj < 8; nj++) {
                #pragma unroll
                for (int e = 0; e < 2; e++) {
                    float v = d[mi][nj][half * 2 + e];
                    if (v > barv) {
                        int p = atomicAdd(&g_cnt[row], 1);
                        if (p < CAP) {
                            g_cidx[(size_t)row * CAP + p] = cb + nj * 8 + e;
                            g_cacc[(size_t)row * CAP + p] = v;
                        }
                    }
                }
            }
        }
    }
}

// ---------------------------------------------------------------------------
// Kernel 2: exact fp32 rescore of survivors + exact finalize (R15 semantics).
// One 128-thread block per row.
// ---------------------------------------------------------------------------
__global__ __launch_bounds__(128)
void rescore_finalize(const float* __restrict__ X, const float* __restrict__ Y,
                      float* __restrict__ out) {
    __shared__ float xrow[K_DIM];
    __shared__ int   s_n;
    __shared__ int   s_idx[RCAP];
    __shared__ float s_ex[RCAP];

    const int row = blockIdx.x;
    const int tid = threadIdx.x;
    const int wid = tid >> 5, lid = tid & 31;

    for (int u = tid; u < K_DIM / 4; u += 128)
        ((float4*)xrow)[u] = ((const float4*)(X + (size_t)row * K_DIM))[u];
    if (tid == 0) s_n = 0;
    __syncthreads();

    // Filter candidates by final screening bar.
    const float barv = ord2f(g_barg[row]) - SCREEN_MARGIN;
    int n = g_cnt[row]; if (n > CAP) n = CAP;
    for (int i = tid; i < n; i += 128) {
        if (g_cacc[(size_t)row * CAP + i] > barv) {
            int p = atomicAdd(&s_n, 1);
            if (p < RCAP) s_idx[p] = g_cidx[(size_t)row * CAP + i];
        }
    }
    __syncthreads();
    int ns = s_n < RCAP ? s_n : RCAP;

    // Exact fp32 dot per survivor (one warp per candidate; fixed reduce order).
    for (int c = wid; c < ns; c += 4) {
        const float* y = Y + (size_t)s_idx[c] * K_DIM;
        float p = 0.0f;
        #pragma unroll
        for (int j = 0; j < 16; j++)
            p = fmaf(xrow[lid * 16 + j], y[lid * 16 + j], p);
        #pragma unroll
        for (int o = 16; o > 0; o >>= 1)
            p = __fadd_rn(p, __shfl_xor_sync(0xffffffff, p, o));
        if (lid == 0) s_ex[c] = p;
    }
    __syncthreads();

    if (tid == 0) {
        // Exact semantics (verbatim from the passing R15 finalize).
        float maxacc = -3.402823466e+38f;
        for (int i = 0; i < ns; i++) maxacc = fmaxf(maxacc, s_ex[i]);
        const float m = __fdiv_rn(maxacc, 0.07f);

        float vv[RCAP]; int vi[RCAP];
        for (int i = 0; i < ns; i++) { vv[i] = __fdiv_rn(s_ex[i], 0.07f); vi[i] = s_idx[i]; }

        for (int i = 1; i < ns; i++) {                 // sort by index asc
            int ii = vi[i]; float tv = vv[i];
            int j = i - 1;
            while (j >= 0 && vi[j] > ii) { vi[j+1] = vi[j]; vv[j+1] = vv[j]; j--; }
            vi[j+1] = ii; vv[j+1] = tv;
        }

        float sum = 0.0f;
        for (int i = 0; i < ns; i++) {
            float dd = __fsub_rn(vv[i], m);
            float p = (float)exp((double)dd);
            if (p < FLT_MIN_NORM) p = 0.0f;
            sum = __fadd_rn(sum, p);
        }
        float lse = __fadd_rn(m, (float)log((double)sum));

        float pv[RCAP];
        for (int i = 0; i < ns; i++) {
            float dd = __fsub_rn(vv[i], lse);
            float p = (float)exp((double)dd);
            if (p < FLT_MIN_NORM) p = 0.0f;
            pv[i] = p;
        }

        int used[16]; int ne = 0;
        float* orow = out + (size_t)row * 16;
        for (int slot = 0; slot < 16; slot++) {
            int best = -1; float bp = 0.0f;
            for (int i = 0; i < ns; i++)
                if (pv[i] > bp) { bp = pv[i]; best = i; }   // ties -> lowest idx
            if (best < 0) break;
            orow[ne] = (float)vi[best];
            used[ne] = vi[best];
            ne++;
            pv[best] = -1.0f;
        }
        int written = ne, v = 0;
        while (written < 16) {
            bool u = false;
            for (int i = 0; i < ne; i++) if (used[i] == v) { u = true; break; }
            if (!u) orow[written++] = (float)v;
            v++;
        }
    }
}

// ---------------------------------------------------------------------------
extern "C" void kernel_launch(void* const* d_in, const int* in_sizes, int n_in,
                              void* d_out, int out_size) {
    const float* X = (const float*)d_in[0];
    const float* Y = (const float*)d_in[1];
    if (in_sizes[0] == N_COLS * K_DIM && in_sizes[1] == M_ROWS * K_DIM) {
        X = (const float*)d_in[1];
        Y = (const float*)d_in[0];
    }
    float* out = (float*)d_out;

    init_kernel<<<(M_ROWS + 255) / 256, 256>>>();
    dim3 grid(M_ROWS / 128, N_COLS / 128);
    screen_gemm<<<grid, 256>>>(X, Y);
    rescore_finalize<<<M_ROWS, 128>>>(X, Y, out);
}